// round 14
// baseline (speedup 1.0000x reference)
#include <cuda_runtime.h>
#include <cuda_bf16.h>
#include <cuda_fp16.h>
#include <cstdint>
#include <cstddef>

// ---------------------------------------------------------------------------
// Problem constants (FluxIPAttnProcessor: B=1, S=2048, H=24, D=128)
// ---------------------------------------------------------------------------
#define S_LEN 2048
#define HIDN  3072
#define NH    24
#define HD    128
#define IPSEQ 512
#define IPDIM 1152

#define DEV_INLINE __device__ __forceinline__

// ---------------------------------------------------------------------------
// PTX helpers: cp.async + ldmatrix + mma.sync (baseline sm_80+ PTX only)
// ---------------------------------------------------------------------------
#define CP_ASYNC16(smaddr, gptr) \
    asm volatile("cp.async.cg.shared.global [%0], [%1], 16;" :: "r"(smaddr), "l"(gptr) : "memory")
#define CP_ASYNC_COMMIT() asm volatile("cp.async.commit_group;" ::: "memory")
#define CP_ASYNC_WAIT(n)  asm volatile("cp.async.wait_group %0;" :: "n"(n) : "memory")

DEV_INLINE void ldsm_x4(uint32_t* r, uint32_t addr) {
    asm volatile("ldmatrix.sync.aligned.m8n8.x4.shared.b16 {%0,%1,%2,%3}, [%4];"
        : "=r"(r[0]), "=r"(r[1]), "=r"(r[2]), "=r"(r[3]) : "r"(addr));
}

DEV_INLINE void mma_bf16(float* d, const uint32_t* a, uint32_t b0, uint32_t b1) {
    asm volatile(
        "mma.sync.aligned.m16n8k16.row.col.f32.bf16.bf16.f32 "
        "{%0,%1,%2,%3}, {%4,%5,%6,%7}, {%8,%9}, {%0,%1,%2,%3};"
        : "+f"(d[0]), "+f"(d[1]), "+f"(d[2]), "+f"(d[3])
        : "r"(a[0]), "r"(a[1]), "r"(a[2]), "r"(a[3]), "r"(b0), "r"(b1));
}

DEV_INLINE void mma_f16(float* d, const uint32_t* a, uint32_t b0, uint32_t b1) {
    asm volatile(
        "mma.sync.aligned.m16n8k16.row.col.f32.f16.f16.f32 "
        "{%0,%1,%2,%3}, {%4,%5,%6,%7}, {%8,%9}, {%0,%1,%2,%3};"
        : "+f"(d[0]), "+f"(d[1]), "+f"(d[2]), "+f"(d[3])
        : "r"(a[0]), "r"(a[1]), "r"(a[2]), "r"(a[3]), "r"(b0), "r"(b1));
}

// pack two f32 -> f16x2 register (lo lane = first arg)
DEV_INLINE uint32_t packf16(float lo, float hi) {
    uint32_t r;
    asm("cvt.rn.f16x2.f32 %0, %1, %2;" : "=r"(r) : "f"(hi), "f"(lo));
    return r;
}

// ---------------------------------------------------------------------------
// Device scratch
// ---------------------------------------------------------------------------
__device__ float g_ao  [S_LEN * HIDN];

// bf16 hi/lo operands (3-term paths)
__device__ __nv_bfloat16 g_hb_hi [S_LEN * HIDN];
__device__ __nv_bfloat16 g_hb_lo [S_LEN * HIDN];
__device__ __nv_bfloat16 g_wq_hi [HIDN * HIDN];
__device__ __nv_bfloat16 g_wq_lo [HIDN * HIDN];
__device__ __nv_bfloat16 g_wk_hi [HIDN * HIDN];
__device__ __nv_bfloat16 g_wk_lo [HIDN * HIDN];
__device__ __nv_bfloat16 g_wkip_hi[HIDN * IPDIM];
__device__ __nv_bfloat16 g_wkip_lo[HIDN * IPDIM];
__device__ __nv_bfloat16 g_ip_hi [IPSEQ * IPDIM];
__device__ __nv_bfloat16 g_ip_lo [IPSEQ * IPDIM];

// fp16 operands (2-term paths)
__device__ __half g_hb16_hi [S_LEN * HIDN];
__device__ __half g_hb16_lo [S_LEN * HIDN];
__device__ __half g_ip16_hi [IPSEQ * IPDIM];
__device__ __half g_ip16_lo [IPSEQ * IPDIM];
__device__ __half g_wv16  [HIDN * HIDN];
__device__ __half g_wvip16[HIDN * IPDIM];
__device__ __half g_wo16  [HIDN * HIDN];
__device__ __half g_ao16_hi [S_LEN * HIDN];
__device__ __half g_ao16_lo [S_LEN * HIDN];

// attention operands (written by GEMM epilogues)
__device__ __nv_bfloat16 g_qr_hi [S_LEN * HIDN];
__device__ __nv_bfloat16 g_qr_lo [S_LEN * HIDN];
__device__ __nv_bfloat16 g_qn_hi [S_LEN * HIDN];
__device__ __nv_bfloat16 g_qn_lo [S_LEN * HIDN];
__device__ __nv_bfloat16 g_kr_hi [S_LEN * HIDN];
__device__ __nv_bfloat16 g_kr_lo [S_LEN * HIDN];
__device__ __nv_bfloat16 g_kipn_hi[IPSEQ * HIDN];
__device__ __nv_bfloat16 g_kipn_lo[IPSEQ * HIDN];
__device__ __half g_vt  [NH * HD * S_LEN];
__device__ __half g_vipt[NH * HD * IPSEQ];

// ---------------------------------------------------------------------------
// Mixed-mode batched conversion
// ---------------------------------------------------------------------------
struct MSet {
    const float* x;
    void* hi;
    void* lo;
    void* hi2;
    void* lo2;
    int n4;
    int mode;
};

__global__ void cvt_mixed(MSet a, MSet b, MSet c, MSet d)
{
    MSet s = (blockIdx.y == 0) ? a : (blockIdx.y == 1) ? b
           : (blockIdx.y == 2) ? c : d;
    int i = blockIdx.x * blockDim.x + threadIdx.x;
    if (i >= s.n4) return;
    float4 v = ((const float4*)s.x)[i];
    float vv[4] = { v.x, v.y, v.z, v.w };

    if (s.mode == 0 || s.mode == 3) {
        __nv_bfloat16 h[4]; float hf[4];
#pragma unroll
        for (int j = 0; j < 4; j++) { h[j] = __float2bfloat16(vv[j]); hf[j] = __bfloat162float(h[j]); }
        __nv_bfloat162 hp0; hp0.x = h[0]; hp0.y = h[1];
        __nv_bfloat162 hp1; hp1.x = h[2]; hp1.y = h[3];
        __nv_bfloat16 l[4];
#pragma unroll
        for (int j = 0; j < 4; j++) l[j] = __float2bfloat16(vv[j] - hf[j]);
        __nv_bfloat162 lp0; lp0.x = l[0]; lp0.y = l[1];
        __nv_bfloat162 lp1; lp1.x = l[2]; lp1.y = l[3];
        ((__nv_bfloat162*)s.hi)[2 * i]     = hp0;
        ((__nv_bfloat162*)s.hi)[2 * i + 1] = hp1;
        ((__nv_bfloat162*)s.lo)[2 * i]     = lp0;
        ((__nv_bfloat162*)s.lo)[2 * i + 1] = lp1;
    }
    if (s.mode == 1 || s.mode == 3) {
        void* oh = (s.mode == 3) ? s.hi2 : s.hi;
        void* ol = (s.mode == 3) ? s.lo2 : s.lo;
        __half h[4]; float hf[4];
#pragma unroll
        for (int j = 0; j < 4; j++) { h[j] = __float2half(vv[j]); hf[j] = __half2float(h[j]); }
        __half2 hp0; hp0.x = h[0]; hp0.y = h[1];
        __half2 hp1; hp1.x = h[2]; hp1.y = h[3];
        __half l[4];
#pragma unroll
        for (int j = 0; j < 4; j++) l[j] = __float2half(vv[j] - hf[j]);
        __half2 lp0; lp0.x = l[0]; lp0.y = l[1];
        __half2 lp1; lp1.x = l[2]; lp1.y = l[3];
        ((__half2*)oh)[2 * i]     = hp0;
        ((__half2*)oh)[2 * i + 1] = hp1;
        ((__half2*)ol)[2 * i]     = lp0;
        ((__half2*)ol)[2 * i + 1] = lp1;
    }
    if (s.mode == 2) {
        __half2 hp0; hp0.x = __float2half(vv[0]); hp0.y = __float2half(vv[1]);
        __half2 hp1; hp1.x = __float2half(vv[2]); hp1.y = __float2half(vv[3]);
        ((__half2*)s.hi)[2 * i]     = hp0;
        ((__half2*)s.hi)[2 * i + 1] = hp1;
    }
}

// ---------------------------------------------------------------------------
// Fused multi-output GEMM with per-set epilogue:
//   two_term 0/1 selects bf16-3term / fp16-2term mainloop.
//   epi_mode: 0 = plain fp32 C+bias
//             1 = fp16 transposed vt output (V path)
//             2 = Q prep: RMSNorm(qscale)->qn pair + RoPE->qr pair
//             3 = K prep: RoPE->kr pair
//             4 = Kip prep: RMSNorm(kscale)->kipn pair
// Prep epilogues are register-lean: all row data stays in smem; outputs
// produced in fully-unrolled 8-element chunks (no local-memory arrays).
// ---------------------------------------------------------------------------
#define KC 64
#define ROWB 144
#define TILEB (128 * ROWB)             // 18432
#define STAGEB (4 * TILEB)             // 73728
#define GEMM_DSMEM (3 * STAGEB)        // 221184
#define EPI_STRIDE 132                 // fp32 stage row stride (padded)

struct GSet {
    const uint16_t* ahi;
    const uint16_t* alo;
    const uint16_t* bhi;
    const uint16_t* blo;
    const float* bias;
    float* C;
    __half* vt_out;
    int vt_len;
    int two_term;
    int epi_mode;
    const float* sinp;
    const float* cosp;
    const float* scale;
    __nv_bfloat16* o1_hi;   // qr / kr / kipn
    __nv_bfloat16* o1_lo;
    __nv_bfloat16* o2_hi;   // qn
    __nv_bfloat16* o2_lo;
};

__global__ void __launch_bounds__(256, 1) gemm_mma_f(
    GSet s0, GSet s1, GSet s2, int nper, int N, int K)
{
    extern __shared__ __align__(128) char smem[];
    const uint32_t sbase = (uint32_t)__cvta_generic_to_shared(smem);
    const int tid  = threadIdx.x;
    const int lane = tid & 31;
    const int w    = tid >> 5;
    const int wm   = w >> 1;
    const int wn   = w & 1;

    const int sel = blockIdx.x / nper;
    const GSet S = (sel == 0) ? s0 : (sel == 1) ? s1 : s2;

    const int m0 = blockIdx.y * 128;
    const int n0 = (blockIdx.x % nper) * 128;
    const int ntiles = S.two_term ? 3 : 4;

    auto load_stage = [&](int buf, int kt) {
        const int k0 = kt * KC;
        const uint32_t sb = sbase + buf * STAGEB;
#pragma unroll
        for (int op = 0; op < 4; op++) {
            if (op >= ntiles) break;
            const uint16_t* src = (op == 0) ? S.ahi : (op == 1) ? S.alo
                                  : (op == 2) ? S.bhi : S.blo;
            const int r0 = (op < 2) ? m0 : n0;
            const uint32_t so = sb + op * TILEB;
#pragma unroll
            for (int it = 0; it < 4; it++) {
                int idx = tid + it * 256;
                int row = idx >> 3;
                int ch  = idx & 7;
                uint32_t sa = so + (uint32_t)(row * ROWB + ch * 16);
                const void* g = (const void*)(src + (size_t)(r0 + row) * K + k0 + ch * 8);
                CP_ASYNC16(sa, g);
            }
        }
        CP_ASYNC_COMMIT();
    };

    float c[2][8][4];
#pragma unroll
    for (int mt = 0; mt < 2; mt++)
#pragma unroll
        for (int nt = 0; nt < 8; nt++)
#pragma unroll
            for (int r = 0; r < 4; r++) c[mt][nt][r] = 0.0f;

    const int T = K / KC;
    load_stage(0, 0);
    if (T > 1) load_stage(1, 1);

    int buf = 0;
#pragma unroll 1
    for (int i = 0; i < T; i++) {
        if (i + 1 < T) { CP_ASYNC_WAIT(1); } else { CP_ASYNC_WAIT(0); }
        __syncthreads();
        if (i + 2 < T) {
            int nb = buf + 2; if (nb >= 3) nb -= 3;
            load_stage(nb, i + 2);
        }

        const uint32_t sb   = sbase + buf * STAGEB;
        const uint32_t sAhi = sb;
        const uint32_t sAlo = sb + TILEB;
        const uint32_t sBhi = sb + 2 * TILEB;
        const uint32_t sBlo = sb + 3 * TILEB;

        if (!S.two_term) {
#pragma unroll
            for (int ks = 0; ks < 4; ks++) {
                uint32_t ah[2][4], al[2][4], bh[4][4], bl[4][4];
#pragma unroll
                for (int mt = 0; mt < 2; mt++) {
                    int row = wm * 32 + mt * 16 + (lane & 15);
                    uint32_t off = (uint32_t)(row * ROWB + (lane >> 4) * 16 + ks * 32);
                    ldsm_x4(ah[mt], sAhi + off);
                    ldsm_x4(al[mt], sAlo + off);
                }
#pragma unroll
                for (int bq = 0; bq < 4; bq++) {
                    int nrow = wn * 64 + bq * 16 + ((lane >> 4) << 3) + (lane & 7);
                    uint32_t off = (uint32_t)(nrow * ROWB + ((lane >> 3) & 1) * 16 + ks * 32);
                    ldsm_x4(bh[bq], sBhi + off);
                    ldsm_x4(bl[bq], sBlo + off);
                }
#pragma unroll
                for (int mt = 0; mt < 2; mt++)
#pragma unroll
                    for (int bq = 0; bq < 4; bq++) {
                        mma_bf16(c[mt][2 * bq],     ah[mt], bh[bq][0], bh[bq][1]);
                        mma_bf16(c[mt][2 * bq + 1], ah[mt], bh[bq][2], bh[bq][3]);
                        mma_bf16(c[mt][2 * bq],     ah[mt], bl[bq][0], bl[bq][1]);
                        mma_bf16(c[mt][2 * bq + 1], ah[mt], bl[bq][2], bl[bq][3]);
                        mma_bf16(c[mt][2 * bq],     al[mt], bh[bq][0], bh[bq][1]);
                        mma_bf16(c[mt][2 * bq + 1], al[mt], bh[bq][2], bh[bq][3]);
                    }
            }
        } else {
#pragma unroll
            for (int ks = 0; ks < 4; ks++) {
                uint32_t ah[2][4], al[2][4], bh[4][4];
#pragma unroll
                for (int mt = 0; mt < 2; mt++) {
                    int row = wm * 32 + mt * 16 + (lane & 15);
                    uint32_t off = (uint32_t)(row * ROWB + (lane >> 4) * 16 + ks * 32);
                    ldsm_x4(ah[mt], sAhi + off);
                    ldsm_x4(al[mt], sAlo + off);
                }
#pragma unroll
                for (int bq = 0; bq < 4; bq++) {
                    int nrow = wn * 64 + bq * 16 + ((lane >> 4) << 3) + (lane & 7);
                    uint32_t off = (uint32_t)(nrow * ROWB + ((lane >> 3) & 1) * 16 + ks * 32);
                    ldsm_x4(bh[bq], sBhi + off);
                }
#pragma unroll
                for (int mt = 0; mt < 2; mt++)
#pragma unroll
                    for (int bq = 0; bq < 4; bq++) {
                        mma_f16(c[mt][2 * bq],     ah[mt], bh[bq][0], bh[bq][1]);
                        mma_f16(c[mt][2 * bq + 1], ah[mt], bh[bq][2], bh[bq][3]);
                        mma_f16(c[mt][2 * bq],     al[mt], bh[bq][0], bh[bq][1]);
                        mma_f16(c[mt][2 * bq + 1], al[mt], bh[bq][2], bh[bq][3]);
                    }
            }
        }
        __syncthreads();
        buf = (buf + 1 == 3) ? 0 : buf + 1;
    }

    const int crow  = wm * 32 + (lane >> 2);
    const int ccol0 = wn * 64 + (lane & 3) * 2;

    if (S.epi_mode == 0) {
#pragma unroll
        for (int mt = 0; mt < 2; mt++) {
#pragma unroll
            for (int nt = 0; nt < 8; nt++) {
                const int r  = m0 + crow + mt * 16;
                const int cc = n0 + ccol0 + nt * 8;
                const float b0v = S.bias[cc], b1v = S.bias[cc + 1];
                float* p  = S.C + (size_t)r * N + cc;
                float* p2 = p + 8 * N;
                p[0]  = c[mt][nt][0] + b0v;
                p[1]  = c[mt][nt][1] + b1v;
                p2[0] = c[mt][nt][2] + b0v;
                p2[1] = c[mt][nt][3] + b1v;
            }
        }
    } else if (S.epi_mode == 1) {
        // fp16 transposed V epilogue
        __half* tr = (__half*)smem;
        __syncthreads();
#pragma unroll
        for (int mt = 0; mt < 2; mt++) {
#pragma unroll
            for (int nt = 0; nt < 8; nt++) {
                const int rl = crow + mt * 16;
                const int cl = ccol0 + nt * 8;
                const float b0v = S.bias[n0 + cl], b1v = S.bias[n0 + cl + 1];
                tr[(cl)     * 128 + rl]     = __float2half(c[mt][nt][0] + b0v);
                tr[(cl + 1) * 128 + rl]     = __float2half(c[mt][nt][1] + b1v);
                tr[(cl)     * 128 + rl + 8] = __float2half(c[mt][nt][2] + b0v);
                tr[(cl + 1) * 128 + rl + 8] = __float2half(c[mt][nt][3] + b1v);
            }
        }
        __syncthreads();
        const int col = tid >> 1, seg = tid & 1;
        __half* dst = S.vt_out + (size_t)(n0 + col) * S.vt_len + m0 + seg * 64;
        const uint4* src = (const uint4*)(tr + col * 128 + seg * 64);
#pragma unroll
        for (int j = 0; j < 8; j++) ((uint4*)dst)[j] = src[j];
    } else {
        // prep epilogues: stage fp32 tile in smem; register-lean processing
        float* tr = (float*)smem;
        __syncthreads();
#pragma unroll
        for (int mt = 0; mt < 2; mt++) {
#pragma unroll
            for (int nt = 0; nt < 8; nt++) {
                const int rl = crow + mt * 16;
                const int cl = ccol0 + nt * 8;
                const float b0v = S.bias[n0 + cl], b1v = S.bias[n0 + cl + 1];
                tr[rl * EPI_STRIDE + cl]           = c[mt][nt][0] + b0v;
                tr[rl * EPI_STRIDE + cl + 1]       = c[mt][nt][1] + b1v;
                tr[(rl + 8) * EPI_STRIDE + cl]     = c[mt][nt][2] + b0v;
                tr[(rl + 8) * EPI_STRIDE + cl + 1] = c[mt][nt][3] + b1v;
            }
        }
        __syncthreads();

        const int r    = tid >> 1;     // local row 0..127
        const int half = tid & 1;      // 0..1 (64-column halves)
        const int srow = m0 + r;
        const float* rowbase = tr + r * EPI_STRIDE;
        const float* rowp = rowbase + half * 64;

        float inv = 0.0f;
        if (S.epi_mode == 2 || S.epi_mode == 4) {
            float ssl = 0.0f;
#pragma unroll
            for (int j = 0; j < 64; j++) { const float v = rowp[j]; ssl += v * v; }
            const float ss = ssl + __shfl_xor_sync(0xffffffffu, ssl, 1);
            const float rms = sqrtf(ss * (1.0f / 128.0f));
            inv = 1.0f / (rms + 1e-6f);
        }

        const size_t obase = (size_t)srow * HIDN + n0 + half * 64;

        if (S.epi_mode == 2 || S.epi_mode == 4) {
            __nv_bfloat16* oh = (S.epi_mode == 2) ? S.o2_hi : S.o1_hi;
            __nv_bfloat16* ol = (S.epi_mode == 2) ? S.o2_lo : S.o1_lo;
#pragma unroll
            for (int cb8 = 0; cb8 < 64; cb8 += 8) {
                __nv_bfloat16 th[8], tl[8];
#pragma unroll
                for (int j = 0; j < 8; j++) {
                    const int d = half * 64 + cb8 + j;
                    const float x = S.scale[d] * rowp[cb8 + j] * inv * 0.08838834764831845f;
                    const __nv_bfloat16 h = __float2bfloat16(x);
                    th[j] = h;
                    tl[j] = __float2bfloat16(x - __bfloat162float(h));
                }
                *(uint4*)(oh + obase + cb8) = *(const uint4*)th;
                *(uint4*)(ol + obase + cb8) = *(const uint4*)tl;
            }
        }
        if (S.epi_mode == 2 || S.epi_mode == 3) {
#pragma unroll
            for (int cb8 = 0; cb8 < 64; cb8 += 8) {
                __nv_bfloat16 th[8], tl[8];
#pragma unroll
                for (int j = 0; j < 8; j++) {
                    const int d = half * 64 + cb8 + j;
                    float x;
                    if (half == 0) {
                        const float rot = (d < 32) ? -rowbase[d + 32] : rowbase[d - 32];
                        x = rowbase[d] * S.cosp[srow * 64 + d] + rot * S.sinp[srow * 64 + d];
                    } else {
                        x = rowbase[d];
                    }
                    const __nv_bfloat16 h = __float2bfloat16(x);
                    th[j] = h;
                    tl[j] = __float2bfloat16(x - __bfloat162float(h));
                }
                *(uint4*)(S.o1_hi + obase + cb8) = *(const uint4*)th;
                *(uint4*)(S.o1_lo + obase + cb8) = *(const uint4*)tl;
            }
        }
    }
}

// ---------------------------------------------------------------------------
// mma.sync fused two-context flash attention (unchanged from R12).
// ---------------------------------------------------------------------------
#define QROWB 272
#define KROWB 272
#define VROWB 144
#define QTILE (128 * QROWB)
#define KTILE (64 * KROWB)
#define VTILE (128 * VROWB)
#define ATT_STAGE (2 * KTILE + VTILE)
#define ATT_SMEM (2 * QTILE + 2 * ATT_STAGE)

__global__ void __launch_bounds__(256, 1) attn_mma(
    const __nv_bfloat16* __restrict__ qr_hi, const __nv_bfloat16* __restrict__ qr_lo,
    const __nv_bfloat16* __restrict__ qn_hi, const __nv_bfloat16* __restrict__ qn_lo,
    const __nv_bfloat16* __restrict__ kr_hi, const __nv_bfloat16* __restrict__ kr_lo,
    const __nv_bfloat16* __restrict__ kip_hi, const __nv_bfloat16* __restrict__ kip_lo,
    const __half* __restrict__ vtp, const __half* __restrict__ viptp,
    float* __restrict__ out,
    __half* __restrict__ out16_hi, __half* __restrict__ out16_lo)
{
    extern __shared__ __align__(128) char smem[];
    const uint32_t sb  = (uint32_t)__cvta_generic_to_shared(smem);
    const uint32_t sQh = sb, sQl = sb + QTILE;
    const uint32_t sSt = sb + 2 * QTILE;

    const int h = blockIdx.y, q0 = blockIdx.x * 128, hofs = h * HD;
    const int tid = threadIdx.x, lane = tid & 31, w = tid >> 5;

    const uint32_t lrowq = (uint32_t)((w * 16 + (lane & 15)) * QROWB + (lane >> 4) * 16);
    const uint32_t lrowk = (uint32_t)((lane & 15) * KROWB + (lane >> 4) * 16);
    const uint32_t lrowv = (uint32_t)((lane & 15) * VROWB + (lane >> 4) * 16);

#pragma unroll 1
    for (int pass = 0; pass < 2; pass++) {
        const __nv_bfloat16* Qh = pass ? qn_hi  : qr_hi;
        const __nv_bfloat16* Ql = pass ? qn_lo  : qr_lo;
        const __nv_bfloat16* Kh = pass ? kip_hi : kr_hi;
        const __nv_bfloat16* Kl = pass ? kip_lo : kr_lo;
        const __half* Vt = pass ? viptp : vtp;
        const int nk = pass ? IPSEQ : S_LEN;
        const int ntiles = nk >> 6;

        __syncthreads();
#pragma unroll
        for (int it = 0; it < 8; it++) {
            int idx = tid + it * 256;
            int row = idx >> 4, ch = idx & 15;
            const size_t g = (size_t)(q0 + row) * HIDN + hofs + ch * 8;
            CP_ASYNC16(sQh + (uint32_t)(row * QROWB + ch * 16), Qh + g);
            CP_ASYNC16(sQl + (uint32_t)(row * QROWB + ch * 16), Ql + g);
        }
        CP_ASYNC_COMMIT();

        auto load_kv = [&](int bufi, int t) {
            const int key0 = t * 64;
            const uint32_t s0 = sSt + bufi * ATT_STAGE;
#pragma unroll
            for (int it = 0; it < 4; it++) {
                int idx = tid + it * 256;
                int row = idx >> 4, ch = idx & 15;
                CP_ASYNC16(s0 + (uint32_t)(row * KROWB + ch * 16),
                           Kh + (size_t)(key0 + row) * HIDN + hofs + ch * 8);
            }
#pragma unroll
            for (int it = 0; it < 4; it++) {
                int idx = tid + it * 256;
                int row = idx >> 4, ch = idx & 15;
                CP_ASYNC16(s0 + KTILE + (uint32_t)(row * KROWB + ch * 16),
                           Kl + (size_t)(key0 + row) * HIDN + hofs + ch * 8);
            }
#pragma unroll
            for (int it = 0; it < 4; it++) {
                int idx = tid + it * 256;
                int row = idx >> 3, ch = idx & 7;
                CP_ASYNC16(s0 + 2 * KTILE + (uint32_t)(row * VROWB + ch * 16),
                           Vt + (size_t)(hofs + row) * nk + key0 + ch * 8);
            }
            CP_ASYNC_COMMIT();
        };

        load_kv(0, 0);
        if (ntiles > 1) load_kv(1, 1);

        uint32_t qh[8][4], ql[8][4];
        CP_ASYNC_WAIT(2);
        __syncthreads();
#pragma unroll
        for (int kk = 0; kk < 8; kk++) {
            ldsm_x4(qh[kk], sQh + lrowq + kk * 32);
            ldsm_x4(ql[kk], sQl + lrowq + kk * 32);
        }

        float mrow[2] = {-1e30f, -1e30f};
        float lrow[2] = {0.0f, 0.0f};
        float o[16][4];
#pragma unroll
        for (int g = 0; g < 16; g++)
#pragma unroll
            for (int r = 0; r < 4; r++) o[g][r] = 0.0f;

#pragma unroll 1
        for (int t = 0; t < ntiles; t++) {
            const int bufi = t & 1;
            if (t + 1 < ntiles) { CP_ASYNC_WAIT(1); } else { CP_ASYNC_WAIT(0); }
            __syncthreads();
            const uint32_t sK  = sSt + bufi * ATT_STAGE;
            const uint32_t sKl = sK + KTILE;
            const uint32_t sV  = sK + 2 * KTILE;

            float s[8][4];
#pragma unroll
            for (int nt = 0; nt < 8; nt++)
#pragma unroll
                for (int r = 0; r < 4; r++) s[nt][r] = 0.0f;

#pragma unroll
            for (int kk = 0; kk < 8; kk++) {
                uint32_t bh[4][4], bl[4][4];
#pragma unroll
                for (int g = 0; g < 4; g++) {
                    ldsm_x4(bh[g], sK  + g * (16 * KROWB) + lrowk + kk * 32);
                    ldsm_x4(bl[g], sKl + g * (16 * KROWB) + lrowk + kk * 32);
                }
#pragma unroll
                for (int g = 0; g < 4; g++) {
                    mma_bf16(s[2 * g],     qh[kk], bh[g][0], bh[g][2]);
                    mma_bf16(s[2 * g + 1], qh[kk], bh[g][1], bh[g][3]);
                }
#pragma unroll
                for (int g = 0; g < 4; g++) {
                    mma_bf16(s[2 * g],     qh[kk], bl[g][0], bl[g][2]);
                    mma_bf16(s[2 * g + 1], qh[kk], bl[g][1], bl[g][3]);
                }
#pragma unroll
                for (int g = 0; g < 4; g++) {
                    mma_bf16(s[2 * g],     ql[kk], bh[g][0], bh[g][2]);
                    mma_bf16(s[2 * g + 1], ql[kk], bh[g][1], bh[g][3]);
                }
            }

#pragma unroll
            for (int i = 0; i < 2; i++) {
                float mx = mrow[i];
#pragma unroll
                for (int nt = 0; nt < 8; nt++)
                    mx = fmaxf(mx, fmaxf(s[nt][2 * i], s[nt][2 * i + 1]));
                mx = fmaxf(mx, __shfl_xor_sync(0xffffffffu, mx, 1));
                mx = fmaxf(mx, __shfl_xor_sync(0xffffffffu, mx, 2));
                const float alpha = __expf(mrow[i] - mx);
                mrow[i] = mx;
                float rs = 0.0f;
#pragma unroll
                for (int nt = 0; nt < 8; nt++) {
                    float p0 = __expf(s[nt][2 * i] - mx);
                    float p1 = __expf(s[nt][2 * i + 1] - mx);
                    s[nt][2 * i] = p0; s[nt][2 * i + 1] = p1;
                    rs += p0 + p1;
                }
                rs += __shfl_xor_sync(0xffffffffu, rs, 1);
                rs += __shfl_xor_sync(0xffffffffu, rs, 2);
                lrow[i] = lrow[i] * alpha + rs;
#pragma unroll
                for (int nt = 0; nt < 16; nt++) {
                    o[nt][2 * i] *= alpha; o[nt][2 * i + 1] *= alpha;
                }
            }

            uint32_t pa[4][4];
#pragma unroll
            for (int j = 0; j < 4; j++) {
                pa[j][0] = packf16(s[2 * j][0],     s[2 * j][1]);
                pa[j][1] = packf16(s[2 * j][2],     s[2 * j][3]);
                pa[j][2] = packf16(s[2 * j + 1][0], s[2 * j + 1][1]);
                pa[j][3] = packf16(s[2 * j + 1][2], s[2 * j + 1][3]);
            }

#pragma unroll
            for (int j = 0; j < 4; j++) {
#pragma unroll
                for (int g = 0; g < 8; g++) {
                    uint32_t vb[4];
                    ldsm_x4(vb, sV + g * (16 * VROWB) + lrowv + j * 32);
                    mma_f16(o[2 * g],     pa[j], vb[0], vb[2]);
                    mma_f16(o[2 * g + 1], pa[j], vb[1], vb[3]);
                }
            }
            __syncthreads();
            if (t + 2 < ntiles) load_kv(bufi, t + 2);
        }

        const float inv0 = 1.0f / lrow[0];
        const float inv1 = 1.0f / lrow[1];
        const int r0 = q0 + w * 16 + (lane >> 2);
        const int cb = hofs + (lane & 3) * 2;
#pragma unroll
        for (int g = 0; g < 16; g++) {
            const size_t i0 = (size_t)r0 * HIDN + cb + g * 8;
            const size_t i1 = (size_t)(r0 + 8) * HIDN + cb + g * 8;
            if (pass == 0) {
                out[i0]     = o[g][0] * inv0; out[i0 + 1] = o[g][1] * inv0;
                out[i1]     = o[g][2] * inv1; out[i1 + 1] = o[g][3] * inv1;
            } else {
                float v00 = out[i0]     + o[g][0] * inv0;
                float v01 = out[i0 + 1] + o[g][1] * inv0;
                float v10 = out[i1]     + o[g][2] * inv1;
                float v11 = out[i1 + 1] + o[g][3] * inv1;
                __half h00 = __float2half(v00), h01 = __float2half(v01);
                __half h10 = __float2half(v10), h11 = __float2half(v11);
                __half2 hh0; hh0.x = h00; hh0.y = h01;
                __half2 hh1; hh1.x = h10; hh1.y = h11;
                __half2 hl0; hl0.x = __float2half(v00 - __half2float(h00));
                hl0.y = __float2half(v01 - __half2float(h01));
                __half2 hl1; hl1.x = __float2half(v10 - __half2float(h10));
                hl1.y = __float2half(v11 - __half2float(h11));
                *(__half2*)(out16_hi + i0) = hh0;
                *(__half2*)(out16_hi + i1) = hh1;
                *(__half2*)(out16_lo + i0) = hl0;
                *(__half2*)(out16_lo + i1) = hl1;
            }
        }
    }
}

// ---------------------------------------------------------------------------
// Launch: two-stream fork/join; prep fused into GEMM epilogues
// ---------------------------------------------------------------------------
extern "C" void kernel_launch(void* const* d_in, const int* in_sizes, int n_in,
                              void* d_out, int out_size)
{
    const float* hidden = (const float*)d_in[0];
    const float* iph    = (const float*)d_in[1];
    const float* sinp   = (const float*)d_in[2];
    const float* cosp   = (const float*)d_in[3];
    const float* Wq     = (const float*)d_in[4];
    const float* bq     = (const float*)d_in[5];
    const float* Wk     = (const float*)d_in[6];
    const float* bk     = (const float*)d_in[7];
    const float* Wv     = (const float*)d_in[8];
    const float* bv     = (const float*)d_in[9];
    const float* Wo     = (const float*)d_in[10];
    const float* bo     = (const float*)d_in[11];
    const float* Wk_ip  = (const float*)d_in[12];
    const float* bk_ip  = (const float*)d_in[13];
    const float* Wv_ip  = (const float*)d_in[14];
    const float* bv_ip  = (const float*)d_in[15];
    const float* qscale = (const float*)d_in[16];
    const float* kscale = (const float*)d_in[17];

    float* ao;
    cudaGetSymbolAddress((void**)&ao, g_ao);

    __nv_bfloat16 *hb_hi, *hb_lo, *wq_hi, *wq_lo, *wk_hi, *wk_lo,
                  *wkip_hi, *wkip_lo, *ip_hi, *ip_lo;
    __nv_bfloat16 *qr_hi, *qr_lo, *qn_hi, *qn_lo, *kr_hi, *kr_lo, *kipn_hi, *kipn_lo;
    __half *hb16_hi, *hb16_lo, *ip16_hi, *ip16_lo, *wv16, *wvip16, *wo16,
           *ao16_hi, *ao16_lo, *vt, *vipt;
    cudaGetSymbolAddress((void**)&hb_hi,   g_hb_hi);
    cudaGetSymbolAddress((void**)&hb_lo,   g_hb_lo);
    cudaGetSymbolAddress((void**)&wq_hi,   g_wq_hi);
    cudaGetSymbolAddress((void**)&wq_lo,   g_wq_lo);
    cudaGetSymbolAddress((void**)&wk_hi,   g_wk_hi);
    cudaGetSymbolAddress((void**)&wk_lo,   g_wk_lo);
    cudaGetSymbolAddress((void**)&wkip_hi, g_wkip_hi);
    cudaGetSymbolAddress((void**)&wkip_lo, g_wkip_lo);
    cudaGetSymbolAddress((void**)&ip_hi,   g_ip_hi);
    cudaGetSymbolAddress((void**)&ip_lo,   g_ip_lo);
    cudaGetSymbolAddress((void**)&qr_hi,   g_qr_hi);
    cudaGetSymbolAddress((void**)&qr_lo,   g_qr_lo);
    cudaGetSymbolAddress((void**)&qn_hi,   g_qn_hi);
    cudaGetSymbolAddress((void**)&qn_lo,   g_qn_lo);
    cudaGetSymbolAddress((void**)&kr_hi,   g_kr_hi);
    cudaGetSymbolAddress((void**)&kr_lo,   g_kr_lo);
    cudaGetSymbolAddress((void**)&kipn_hi, g_kipn_hi);
    cudaGetSymbolAddress((void**)&kipn_lo, g_kipn_lo);
    cudaGetSymbolAddress((void**)&hb16_hi, g_hb16_hi);
    cudaGetSymbolAddress((void**)&hb16_lo, g_hb16_lo);
    cudaGetSymbolAddress((void**)&ip16_hi, g_ip16_hi);
    cudaGetSymbolAddress((void**)&ip16_lo, g_ip16_lo);
    cudaGetSymbolAddress((void**)&wv16,    g_wv16);
    cudaGetSymbolAddress((void**)&wvip16,  g_wvip16);
    cudaGetSymbolAddress((void**)&wo16,    g_wo16);
    cudaGetSymbolAddress((void**)&ao16_hi, g_ao16_hi);
    cudaGetSymbolAddress((void**)&ao16_lo, g_ao16_lo);
    cudaGetSymbolAddress((void**)&vt,      g_vt);
    cudaGetSymbolAddress((void**)&vipt,    g_vipt);

    static cudaStream_t sB = nullptr;
    static cudaEvent_t evFork = nullptr, evJoin = nullptr;
    if (!sB) {
        cudaStreamCreateWithFlags(&sB, cudaStreamNonBlocking);
        cudaEventCreateWithFlags(&evFork, cudaEventDisableTiming);
        cudaEventCreateWithFlags(&evJoin, cudaEventDisableTiming);
    }

    const int n4w   = HIDN * HIDN / 4;
    const int n4ipw = HIDN * IPDIM / 4;
    const int n4h   = S_LEN * HIDN / 4;
    const int n4ip  = IPSEQ * IPDIM / 4;

    cudaFuncSetAttribute(gemm_mma_f, cudaFuncAttributeMaxDynamicSharedMemorySize, GEMM_DSMEM);
    cudaFuncSetAttribute(attn_mma, cudaFuncAttributeMaxDynamicSharedMemorySize, ATT_SMEM);

    cudaEventRecord(evFork, 0);
    cudaStreamWaitEvent(sB, evFork, 0);

    // ---- stream A: conversions for QKV path ----
    {
        MSet a = { Wq, wq_hi, wq_lo, nullptr, nullptr, n4w, 0 };
        MSet b = { Wk, wk_hi, wk_lo, nullptr, nullptr, n4w, 0 };
        MSet c = { hidden, hb_hi, hb_lo, hb16_hi, hb16_lo, n4h, 3 };
        MSet d = { Wv, wv16, nullptr, nullptr, nullptr, n4w, 2 };
        cvt_mixed<<<dim3((n4w + 255) / 256, 4), 256>>>(a, b, c, d);
    }
    // ---- stream B: conversions for IP + Wo paths ----
    {
        MSet a = { Wk_ip, wkip_hi, wkip_lo, nullptr, nullptr, n4ipw, 0 };
        MSet b = { iph, ip_hi, ip_lo, ip16_hi, ip16_lo, n4ip, 3 };
        MSet c = { Wv_ip, wvip16, nullptr, nullptr, nullptr, n4ipw, 2 };
        MSet d = { Wo, wo16, nullptr, nullptr, nullptr, n4w, 2 };
        cvt_mixed<<<dim3((n4w + 255) / 256, 4), 256, 0, sB>>>(a, b, c, d);
    }

    // ---- stream A: fused QKV projection with prep epilogues ----
    {
        GSet sq = { (const uint16_t*)hb_hi,   (const uint16_t*)hb_lo,
                    (const uint16_t*)wq_hi,   (const uint16_t*)wq_lo,   bq, nullptr,
                    nullptr, 0, 0, 2, sinp, cosp, qscale,
                    qr_hi, qr_lo, qn_hi, qn_lo };
        GSet sk = { (const uint16_t*)hb_hi,   (const uint16_t*)hb_lo,
                    (const uint16_t*)wk_hi,   (const uint16_t*)wk_lo,   bk, nullptr,
                    nullptr, 0, 0, 3, sinp, cosp, nullptr,
                    kr_hi, kr_lo, nullptr, nullptr };
        GSet sv = { (const uint16_t*)hb16_hi, (const uint16_t*)hb16_lo,
                    (const uint16_t*)wv16,    nullptr,                  bv, nullptr,
                    vt, S_LEN, 1, 1, nullptr, nullptr, nullptr,
                    nullptr, nullptr, nullptr, nullptr };
        gemm_mma_f<<<dim3(3 * (HIDN / 128), S_LEN / 128), 256, GEMM_DSMEM>>>(
            sq, sk, sv, HIDN / 128, HIDN, HIDN);
    }
    // ---- stream B: fused IP projection with kip-norm epilogue ----
    {
        GSet sk = { (const uint16_t*)ip_hi,   (const uint16_t*)ip_lo,
                    (const uint16_t*)wkip_hi, (const uint16_t*)wkip_lo, bk_ip, nullptr,
                    nullptr, 0, 0, 4, nullptr, nullptr, kscale,
                    kipn_hi, kipn_lo, nullptr, nullptr };
        GSet sv = { (const uint16_t*)ip16_hi, (const uint16_t*)ip16_lo,
                    (const uint16_t*)wvip16,  nullptr,                  bv_ip, nullptr,
                    vipt, IPSEQ, 1, 1, nullptr, nullptr, nullptr,
                    nullptr, nullptr, nullptr, nullptr };
        gemm_mma_f<<<dim3(2 * (HIDN / 128), IPSEQ / 128), 256, GEMM_DSMEM, sB>>>(
            sk, sv, sv, HIDN / 128, HIDN, IPDIM);
    }

    // ---- join ----
    cudaEventRecord(evJoin, sB);
    cudaStreamWaitEvent(0, evJoin, 0);

    // ---- attention (pass1 writes ao16 hi/lo directly) ----
    attn_mma<<<dim3(S_LEN / 128, NH), 256, ATT_SMEM>>>(
        qr_hi, qr_lo, qn_hi, qn_lo, kr_hi, kr_lo, kipn_hi, kipn_lo, vt, vipt,
        ao, ao16_hi, ao16_lo);

    // ---- output projection (fp16 2-term) ----
    {
        GSet so = { (const uint16_t*)ao16_hi, (const uint16_t*)ao16_lo,
                    (const uint16_t*)wo16,    nullptr, bo, (float*)d_out,
                    nullptr, 0, 1, 0, nullptr, nullptr, nullptr,
                    nullptr, nullptr, nullptr, nullptr };
        gemm_mma_f<<<dim3(HIDN / 128, S_LEN / 128), 256, GEMM_DSMEM>>>(
            so, so, so, HIDN / 128, HIDN, HIDN);
    }
}

// round 15
// speedup vs baseline: 1.0292x; 1.0292x over previous
#include <cuda_runtime.h>
#include <cuda_bf16.h>
#include <cuda_fp16.h>
#include <cstdint>
#include <cstddef>

// ---------------------------------------------------------------------------
// Problem constants (FluxIPAttnProcessor: B=1, S=2048, H=24, D=128)
// ---------------------------------------------------------------------------
#define S_LEN 2048
#define HIDN  3072
#define NH    24
#define HD    128
#define IPSEQ 512
#define IPDIM 1152

#define DEV_INLINE __device__ __forceinline__

// ---------------------------------------------------------------------------
// PTX helpers: cp.async + ldmatrix + mma.sync (baseline sm_80+ PTX only)
// ---------------------------------------------------------------------------
#define CP_ASYNC16(smaddr, gptr) \
    asm volatile("cp.async.cg.shared.global [%0], [%1], 16;" :: "r"(smaddr), "l"(gptr) : "memory")
#define CP_ASYNC_COMMIT() asm volatile("cp.async.commit_group;" ::: "memory")
#define CP_ASYNC_WAIT(n)  asm volatile("cp.async.wait_group %0;" :: "n"(n) : "memory")

DEV_INLINE void ldsm_x4(uint32_t* r, uint32_t addr) {
    asm volatile("ldmatrix.sync.aligned.m8n8.x4.shared.b16 {%0,%1,%2,%3}, [%4];"
        : "=r"(r[0]), "=r"(r[1]), "=r"(r[2]), "=r"(r[3]) : "r"(addr));
}

DEV_INLINE void mma_bf16(float* d, const uint32_t* a, uint32_t b0, uint32_t b1) {
    asm volatile(
        "mma.sync.aligned.m16n8k16.row.col.f32.bf16.bf16.f32 "
        "{%0,%1,%2,%3}, {%4,%5,%6,%7}, {%8,%9}, {%0,%1,%2,%3};"
        : "+f"(d[0]), "+f"(d[1]), "+f"(d[2]), "+f"(d[3])
        : "r"(a[0]), "r"(a[1]), "r"(a[2]), "r"(a[3]), "r"(b0), "r"(b1));
}

DEV_INLINE void mma_f16(float* d, const uint32_t* a, uint32_t b0, uint32_t b1) {
    asm volatile(
        "mma.sync.aligned.m16n8k16.row.col.f32.f16.f16.f32 "
        "{%0,%1,%2,%3}, {%4,%5,%6,%7}, {%8,%9}, {%0,%1,%2,%3};"
        : "+f"(d[0]), "+f"(d[1]), "+f"(d[2]), "+f"(d[3])
        : "r"(a[0]), "r"(a[1]), "r"(a[2]), "r"(a[3]), "r"(b0), "r"(b1));
}

// pack two f32 -> f16x2 register (lo lane = first arg)
DEV_INLINE uint32_t packf16(float lo, float hi) {
    uint32_t r;
    asm("cvt.rn.f16x2.f32 %0, %1, %2;" : "=r"(r) : "f"(hi), "f"(lo));
    return r;
}
DEV_INLINE void unpackf16(uint32_t v, float& lo, float& hi) {
    __half2 h = *(__half2*)&v;
    lo = __half2float(h.x);
    hi = __half2float(h.y);
}

// ---------------------------------------------------------------------------
// Device scratch
// ---------------------------------------------------------------------------
__device__ float g_q   [S_LEN * HIDN];
__device__ float g_k   [S_LEN * HIDN];
__device__ float g_kip [IPSEQ * HIDN];

// bf16 hi/lo operands (3-term paths)
__device__ __nv_bfloat16 g_hb_hi [S_LEN * HIDN];
__device__ __nv_bfloat16 g_hb_lo [S_LEN * HIDN];
__device__ __nv_bfloat16 g_wq_hi [HIDN * HIDN];
__device__ __nv_bfloat16 g_wq_lo [HIDN * HIDN];
__device__ __nv_bfloat16 g_wk_hi [HIDN * HIDN];
__device__ __nv_bfloat16 g_wk_lo [HIDN * HIDN];
__device__ __nv_bfloat16 g_wkip_hi[HIDN * IPDIM];
__device__ __nv_bfloat16 g_wkip_lo[HIDN * IPDIM];
__device__ __nv_bfloat16 g_ip_hi [IPSEQ * IPDIM];
__device__ __nv_bfloat16 g_ip_lo [IPSEQ * IPDIM];

// fp16 operands (2-term paths)
__device__ __half g_hb16_hi [S_LEN * HIDN];
__device__ __half g_hb16_lo [S_LEN * HIDN];
__device__ __half g_ip16_hi [IPSEQ * IPDIM];
__device__ __half g_ip16_lo [IPSEQ * IPDIM];
__device__ __half g_wv16  [HIDN * HIDN];
__device__ __half g_wvip16[HIDN * IPDIM];
__device__ __half g_wo16  [HIDN * HIDN];
__device__ __half g_ao16_hi [S_LEN * HIDN];
__device__ __half g_ao16_lo [S_LEN * HIDN];

// attention operands (bf16 hi/lo) + fp16 transposed V (written by GEMM epilogue)
__device__ __nv_bfloat16 g_qr_hi [S_LEN * HIDN];
__device__ __nv_bfloat16 g_qr_lo [S_LEN * HIDN];
__device__ __nv_bfloat16 g_qn_hi [S_LEN * HIDN];
__device__ __nv_bfloat16 g_qn_lo [S_LEN * HIDN];
__device__ __nv_bfloat16 g_kr_hi [S_LEN * HIDN];
__device__ __nv_bfloat16 g_kr_lo [S_LEN * HIDN];
__device__ __nv_bfloat16 g_kipn_hi[IPSEQ * HIDN];
__device__ __nv_bfloat16 g_kipn_lo[IPSEQ * HIDN];
__device__ __half g_vt  [NH * HD * S_LEN];
__device__ __half g_vipt[NH * HD * IPSEQ];

// ---------------------------------------------------------------------------
// Mixed-mode batched conversion
// ---------------------------------------------------------------------------
struct MSet {
    const float* x;
    void* hi;
    void* lo;
    void* hi2;
    void* lo2;
    int n4;
    int mode;
};

__global__ void cvt_mixed(MSet a, MSet b, MSet c, MSet d)
{
    MSet s = (blockIdx.y == 0) ? a : (blockIdx.y == 1) ? b
           : (blockIdx.y == 2) ? c : d;
    int i = blockIdx.x * blockDim.x + threadIdx.x;
    if (i >= s.n4) return;
    float4 v = ((const float4*)s.x)[i];
    float vv[4] = { v.x, v.y, v.z, v.w };

    if (s.mode == 0 || s.mode == 3) {
        __nv_bfloat16 h[4]; float hf[4];
#pragma unroll
        for (int j = 0; j < 4; j++) { h[j] = __float2bfloat16(vv[j]); hf[j] = __bfloat162float(h[j]); }
        __nv_bfloat162 hp0; hp0.x = h[0]; hp0.y = h[1];
        __nv_bfloat162 hp1; hp1.x = h[2]; hp1.y = h[3];
        __nv_bfloat16 l[4];
#pragma unroll
        for (int j = 0; j < 4; j++) l[j] = __float2bfloat16(vv[j] - hf[j]);
        __nv_bfloat162 lp0; lp0.x = l[0]; lp0.y = l[1];
        __nv_bfloat162 lp1; lp1.x = l[2]; lp1.y = l[3];
        ((__nv_bfloat162*)s.hi)[2 * i]     = hp0;
        ((__nv_bfloat162*)s.hi)[2 * i + 1] = hp1;
        ((__nv_bfloat162*)s.lo)[2 * i]     = lp0;
        ((__nv_bfloat162*)s.lo)[2 * i + 1] = lp1;
    }
    if (s.mode == 1 || s.mode == 3) {
        void* oh = (s.mode == 3) ? s.hi2 : s.hi;
        void* ol = (s.mode == 3) ? s.lo2 : s.lo;
        __half h[4]; float hf[4];
#pragma unroll
        for (int j = 0; j < 4; j++) { h[j] = __float2half(vv[j]); hf[j] = __half2float(h[j]); }
        __half2 hp0; hp0.x = h[0]; hp0.y = h[1];
        __half2 hp1; hp1.x = h[2]; hp1.y = h[3];
        __half l[4];
#pragma unroll
        for (int j = 0; j < 4; j++) l[j] = __float2half(vv[j] - hf[j]);
        __half2 lp0; lp0.x = l[0]; lp0.y = l[1];
        __half2 lp1; lp1.x = l[2]; lp1.y = l[3];
        ((__half2*)oh)[2 * i]     = hp0;
        ((__half2*)oh)[2 * i + 1] = hp1;
        ((__half2*)ol)[2 * i]     = lp0;
        ((__half2*)ol)[2 * i + 1] = lp1;
    }
    if (s.mode == 2) {
        __half2 hp0; hp0.x = __float2half(vv[0]); hp0.y = __float2half(vv[1]);
        __half2 hp1; hp1.x = __float2half(vv[2]); hp1.y = __float2half(vv[3]);
        ((__half2*)s.hi)[2 * i]     = hp0;
        ((__half2*)s.hi)[2 * i + 1] = hp1;
    }
}

// ---------------------------------------------------------------------------
// Fused multi-output GEMM. two_term=0: bf16 3-term; two_term=1: fp16 2-term.
// If vt_out != null, epilogue writes fp16 TRANSPOSED output vt[cc][r]
// via smem staging instead of fp32 C.  (R12 configuration — best measured.)
// ---------------------------------------------------------------------------
#define KC 64
#define ROWB 144
#define TILEB (128 * ROWB)             // 18432
#define STAGEB (4 * TILEB)             // 73728
#define GEMM_DSMEM (3 * STAGEB)        // 221184

struct GSet {
    const uint16_t* ahi;
    const uint16_t* alo;
    const uint16_t* bhi;
    const uint16_t* blo;
    const float* bias;
    float* C;
    __half* vt_out;
    int vt_len;
    int two_term;
};

__global__ void __launch_bounds__(256, 1) gemm_mma_f(
    GSet s0, GSet s1, GSet s2, int nper, int N, int K)
{
    extern __shared__ __align__(128) char smem[];
    const uint32_t sbase = (uint32_t)__cvta_generic_to_shared(smem);
    const int tid  = threadIdx.x;
    const int lane = tid & 31;
    const int w    = tid >> 5;
    const int wm   = w >> 1;
    const int wn   = w & 1;

    const int sel = blockIdx.x / nper;
    const GSet S = (sel == 0) ? s0 : (sel == 1) ? s1 : s2;

    const int m0 = blockIdx.y * 128;
    const int n0 = (blockIdx.x % nper) * 128;
    const int ntiles = S.two_term ? 3 : 4;

    auto load_stage = [&](int buf, int kt) {
        const int k0 = kt * KC;
        const uint32_t sb = sbase + buf * STAGEB;
#pragma unroll
        for (int op = 0; op < 4; op++) {
            if (op >= ntiles) break;
            const uint16_t* src = (op == 0) ? S.ahi : (op == 1) ? S.alo
                                  : (op == 2) ? S.bhi : S.blo;
            const int r0 = (op < 2) ? m0 : n0;
            const uint32_t so = sb + op * TILEB;
#pragma unroll
            for (int it = 0; it < 4; it++) {
                int idx = tid + it * 256;
                int row = idx >> 3;
                int ch  = idx & 7;
                uint32_t sa = so + (uint32_t)(row * ROWB + ch * 16);
                const void* g = (const void*)(src + (size_t)(r0 + row) * K + k0 + ch * 8);
                CP_ASYNC16(sa, g);
            }
        }
        CP_ASYNC_COMMIT();
    };

    float c[2][8][4];
#pragma unroll
    for (int mt = 0; mt < 2; mt++)
#pragma unroll
        for (int nt = 0; nt < 8; nt++)
#pragma unroll
            for (int r = 0; r < 4; r++) c[mt][nt][r] = 0.0f;

    const int T = K / KC;
    load_stage(0, 0);
    if (T > 1) load_stage(1, 1);

    int buf = 0;
#pragma unroll 1
    for (int i = 0; i < T; i++) {
        if (i + 1 < T) { CP_ASYNC_WAIT(1); } else { CP_ASYNC_WAIT(0); }
        __syncthreads();
        if (i + 2 < T) {
            int nb = buf + 2; if (nb >= 3) nb -= 3;
            load_stage(nb, i + 2);
        }

        const uint32_t sb   = sbase + buf * STAGEB;
        const uint32_t sAhi = sb;
        const uint32_t sAlo = sb + TILEB;
        const uint32_t sBhi = sb + 2 * TILEB;
        const uint32_t sBlo = sb + 3 * TILEB;

        if (!S.two_term) {
#pragma unroll
            for (int ks = 0; ks < 4; ks++) {
                uint32_t ah[2][4], al[2][4], bh[4][4], bl[4][4];
#pragma unroll
                for (int mt = 0; mt < 2; mt++) {
                    int row = wm * 32 + mt * 16 + (lane & 15);
                    uint32_t off = (uint32_t)(row * ROWB + (lane >> 4) * 16 + ks * 32);
                    ldsm_x4(ah[mt], sAhi + off);
                    ldsm_x4(al[mt], sAlo + off);
                }
#pragma unroll
                for (int bq = 0; bq < 4; bq++) {
                    int nrow = wn * 64 + bq * 16 + ((lane >> 4) << 3) + (lane & 7);
                    uint32_t off = (uint32_t)(nrow * ROWB + ((lane >> 3) & 1) * 16 + ks * 32);
                    ldsm_x4(bh[bq], sBhi + off);
                    ldsm_x4(bl[bq], sBlo + off);
                }
#pragma unroll
                for (int mt = 0; mt < 2; mt++)
#pragma unroll
                    for (int bq = 0; bq < 4; bq++) {
                        mma_bf16(c[mt][2 * bq],     ah[mt], bh[bq][0], bh[bq][1]);
                        mma_bf16(c[mt][2 * bq + 1], ah[mt], bh[bq][2], bh[bq][3]);
                        mma_bf16(c[mt][2 * bq],     ah[mt], bl[bq][0], bl[bq][1]);
                        mma_bf16(c[mt][2 * bq + 1], ah[mt], bl[bq][2], bl[bq][3]);
                        mma_bf16(c[mt][2 * bq],     al[mt], bh[bq][0], bh[bq][1]);
                        mma_bf16(c[mt][2 * bq + 1], al[mt], bh[bq][2], bh[bq][3]);
                    }
            }
        } else {
#pragma unroll
            for (int ks = 0; ks < 4; ks++) {
                uint32_t ah[2][4], al[2][4], bh[4][4];
#pragma unroll
                for (int mt = 0; mt < 2; mt++) {
                    int row = wm * 32 + mt * 16 + (lane & 15);
                    uint32_t off = (uint32_t)(row * ROWB + (lane >> 4) * 16 + ks * 32);
                    ldsm_x4(ah[mt], sAhi + off);
                    ldsm_x4(al[mt], sAlo + off);
                }
#pragma unroll
                for (int bq = 0; bq < 4; bq++) {
                    int nrow = wn * 64 + bq * 16 + ((lane >> 4) << 3) + (lane & 7);
                    uint32_t off = (uint32_t)(nrow * ROWB + ((lane >> 3) & 1) * 16 + ks * 32);
                    ldsm_x4(bh[bq], sBhi + off);
                }
#pragma unroll
                for (int mt = 0; mt < 2; mt++)
#pragma unroll
                    for (int bq = 0; bq < 4; bq++) {
                        mma_f16(c[mt][2 * bq],     ah[mt], bh[bq][0], bh[bq][1]);
                        mma_f16(c[mt][2 * bq + 1], ah[mt], bh[bq][2], bh[bq][3]);
                        mma_f16(c[mt][2 * bq],     al[mt], bh[bq][0], bh[bq][1]);
                        mma_f16(c[mt][2 * bq + 1], al[mt], bh[bq][2], bh[bq][3]);
                    }
            }
        }
        __syncthreads();
        buf = (buf + 1 == 3) ? 0 : buf + 1;
    }

    const int crow  = wm * 32 + (lane >> 2);
    const int ccol0 = wn * 64 + (lane & 3) * 2;

    if (S.vt_out == nullptr) {
#pragma unroll
        for (int mt = 0; mt < 2; mt++) {
#pragma unroll
            for (int nt = 0; nt < 8; nt++) {
                const int r  = m0 + crow + mt * 16;
                const int cc = n0 + ccol0 + nt * 8;
                const float b0v = S.bias[cc], b1v = S.bias[cc + 1];
                float* p  = S.C + (size_t)r * N + cc;
                float* p2 = p + 8 * N;
                p[0]  = c[mt][nt][0] + b0v;
                p[1]  = c[mt][nt][1] + b1v;
                p2[0] = c[mt][nt][2] + b0v;
                p2[1] = c[mt][nt][3] + b1v;
            }
        }
    } else {
        // Transposed fp16 epilogue via smem staging
        __half* tr = (__half*)smem;
        __syncthreads();
#pragma unroll
        for (int mt = 0; mt < 2; mt++) {
#pragma unroll
            for (int nt = 0; nt < 8; nt++) {
                const int rl = crow + mt * 16;
                const int cl = ccol0 + nt * 8;
                const float b0v = S.bias[n0 + cl], b1v = S.bias[n0 + cl + 1];
                tr[(cl)     * 128 + rl]     = __float2half(c[mt][nt][0] + b0v);
                tr[(cl + 1) * 128 + rl]     = __float2half(c[mt][nt][1] + b1v);
                tr[(cl)     * 128 + rl + 8] = __float2half(c[mt][nt][2] + b0v);
                tr[(cl + 1) * 128 + rl + 8] = __float2half(c[mt][nt][3] + b1v);
            }
        }
        __syncthreads();
        const int col = tid >> 1, seg = tid & 1;
        __half* dst = S.vt_out + (size_t)(n0 + col) * S.vt_len + m0 + seg * 64;
        const uint4* src = (const uint4*)(tr + col * 128 + seg * 64);
#pragma unroll
        for (int j = 0; j < 8; j++) ((uint4*)dst)[j] = src[j];
    }
}

// ---------------------------------------------------------------------------
// Prep kernels (R12 versions): merged Q+K RoPE/RMSNorm, separate Kip
// ---------------------------------------------------------------------------
DEV_INLINE float blk_sumsq(float x, float* red, int d) {
    float v = x * x;
#pragma unroll
    for (int o = 16; o > 0; o >>= 1) v += __shfl_xor_sync(0xffffffffu, v, o);
    if ((d & 31) == 0) red[d >> 5] = v;
    __syncthreads();
    return red[0] + red[1] + red[2] + red[3];
}

DEV_INLINE void split_store(__nv_bfloat16* hi, __nv_bfloat16* lo, size_t idx, float x) {
    __nv_bfloat16 h = __float2bfloat16(x);
    hi[idx] = h;
    lo[idx] = __float2bfloat16(x - __bfloat162float(h));
}

__global__ void prep_qk_kernel(const float* __restrict__ q, const float* __restrict__ k,
                               const float* __restrict__ sinp, const float* __restrict__ cosp,
                               const float* __restrict__ qscale,
                               __nv_bfloat16* __restrict__ qr_hi, __nv_bfloat16* __restrict__ qr_lo,
                               __nv_bfloat16* __restrict__ qn_hi, __nv_bfloat16* __restrict__ qn_lo,
                               __nv_bfloat16* __restrict__ kr_hi, __nv_bfloat16* __restrict__ kr_lo)
{
    __shared__ float red[4];
    const int s = blockIdx.x, hh = blockIdx.y, d = threadIdx.x;
    const size_t base = (size_t)s * HIDN + hh * HD;
    const float xq = q[base + d];
    const float ss = blk_sumsq(xq, red, d);
    const float rms = sqrtf(ss * (1.0f / 128.0f));
    const float inv = 1.0f / (rms + 1e-6f);
    split_store(qn_hi, qn_lo, base + d, qscale[d] * xq * inv * 0.08838834764831845f);

    const float sv = (d < 64) ? sinp[s * 64 + d] : 0.0f;
    const float cv = (d < 64) ? cosp[s * 64 + d] : 0.0f;

    float oq;
    if (d < 64) {
        float rot = (d < 32) ? -q[base + d + 32] : q[base + d - 32];
        oq = xq * cv + rot * sv;
    } else {
        oq = xq;
    }
    split_store(qr_hi, qr_lo, base + d, oq);

    const float xk = k[base + d];
    float ok;
    if (d < 64) {
        float rot = (d < 32) ? -k[base + d + 32] : k[base + d - 32];
        ok = xk * cv + rot * sv;
    } else {
        ok = xk;
    }
    split_store(kr_hi, kr_lo, base + d, ok);
}

__global__ void prep_kip_kernel(const float* __restrict__ kip,
                                const float* __restrict__ kscale,
                                __nv_bfloat16* __restrict__ kn_hi, __nv_bfloat16* __restrict__ kn_lo)
{
    __shared__ float red[4];
    const int s = blockIdx.x, hh = blockIdx.y, d = threadIdx.x;
    const size_t base = (size_t)s * HIDN + hh * HD;
    const float x = kip[base + d];
    const float ss = blk_sumsq(x, red, d);
    const float rms = sqrtf(ss * (1.0f / 128.0f));
    const float inv = 1.0f / (rms + 1e-6f);
    split_store(kn_hi, kn_lo, base + d, kscale[d] * x * inv * 0.08838834764831845f);
}

// ---------------------------------------------------------------------------
// mma.sync fused two-context flash attention.
// Cross-pass accumulation is register-resident: pass 0 result held as packed
// fp16x2 (32 regs); pass 1 adds and emits the fp16 hi/lo pair for Wo.
// No fp32 intermediate buffer.
// ---------------------------------------------------------------------------
#define QROWB 272
#define KROWB 272
#define VROWB 144
#define QTILE (128 * QROWB)
#define KTILE (64 * KROWB)
#define VTILE (128 * VROWB)
#define ATT_STAGE (2 * KTILE + VTILE)
#define ATT_SMEM (2 * QTILE + 2 * ATT_STAGE)

__global__ void __launch_bounds__(256, 1) attn_mma(
    const __nv_bfloat16* __restrict__ qr_hi, const __nv_bfloat16* __restrict__ qr_lo,
    const __nv_bfloat16* __restrict__ qn_hi, const __nv_bfloat16* __restrict__ qn_lo,
    const __nv_bfloat16* __restrict__ kr_hi, const __nv_bfloat16* __restrict__ kr_lo,
    const __nv_bfloat16* __restrict__ kip_hi, const __nv_bfloat16* __restrict__ kip_lo,
    const __half* __restrict__ vtp, const __half* __restrict__ viptp,
    __half* __restrict__ out16_hi, __half* __restrict__ out16_lo)
{
    extern __shared__ __align__(128) char smem[];
    const uint32_t sb  = (uint32_t)__cvta_generic_to_shared(smem);
    const uint32_t sQh = sb, sQl = sb + QTILE;
    const uint32_t sSt = sb + 2 * QTILE;

    const int h = blockIdx.y, q0 = blockIdx.x * 128, hofs = h * HD;
    const int tid = threadIdx.x, lane = tid & 31, w = tid >> 5;

    const uint32_t lrowq = (uint32_t)((w * 16 + (lane & 15)) * QROWB + (lane >> 4) * 16);
    const uint32_t lrowk = (uint32_t)((lane & 15) * KROWB + (lane >> 4) * 16);
    const uint32_t lrowv = (uint32_t)((lane & 15) * VROWB + (lane >> 4) * 16);

    // pass-0 result, packed fp16x2: acc16[g][0] = rows (r0, r0+8) col cb;
    uint32_t acc16[16][2];

#pragma unroll 1
    for (int pass = 0; pass < 2; pass++) {
        const __nv_bfloat16* Qh = pass ? qn_hi  : qr_hi;
        const __nv_bfloat16* Ql = pass ? qn_lo  : qr_lo;
        const __nv_bfloat16* Kh = pass ? kip_hi : kr_hi;
        const __nv_bfloat16* Kl = pass ? kip_lo : kr_lo;
        const __half* Vt = pass ? viptp : vtp;
        const int nk = pass ? IPSEQ : S_LEN;
        const int ntiles = nk >> 6;

        __syncthreads();
#pragma unroll
        for (int it = 0; it < 8; it++) {
            int idx = tid + it * 256;
            int row = idx >> 4, ch = idx & 15;
            const size_t g = (size_t)(q0 + row) * HIDN + hofs + ch * 8;
            CP_ASYNC16(sQh + (uint32_t)(row * QROWB + ch * 16), Qh + g);
            CP_ASYNC16(sQl + (uint32_t)(row * QROWB + ch * 16), Ql + g);
        }
        CP_ASYNC_COMMIT();

        auto load_kv = [&](int bufi, int t) {
            const int key0 = t * 64;
            const uint32_t s0 = sSt + bufi * ATT_STAGE;
#pragma unroll
            for (int it = 0; it < 4; it++) {
                int idx = tid + it * 256;
                int row = idx >> 4, ch = idx & 15;
                CP_ASYNC16(s0 + (uint32_t)(row * KROWB + ch * 16),
                           Kh + (size_t)(key0 + row) * HIDN + hofs + ch * 8);
            }
#pragma unroll
            for (int it = 0; it < 4; it++) {
                int idx = tid + it * 256;
                int row = idx >> 4, ch = idx & 15;
                CP_ASYNC16(s0 + KTILE + (uint32_t)(row * KROWB + ch * 16),
                           Kl + (size_t)(key0 + row) * HIDN + hofs + ch * 8);
            }
#pragma unroll
            for (int it = 0; it < 4; it++) {
                int idx = tid + it * 256;
                int row = idx >> 3, ch = idx & 7;
                CP_ASYNC16(s0 + 2 * KTILE + (uint32_t)(row * VROWB + ch * 16),
                           Vt + (size_t)(hofs + row) * nk + key0 + ch * 8);
            }
            CP_ASYNC_COMMIT();
        };

        load_kv(0, 0);
        if (ntiles > 1) load_kv(1, 1);

        uint32_t qh[8][4], ql[8][4];
        CP_ASYNC_WAIT(2);
        __syncthreads();
#pragma unroll
        for (int kk = 0; kk < 8; kk++) {
            ldsm_x4(qh[kk], sQh + lrowq + kk * 32);
            ldsm_x4(ql[kk], sQl + lrowq + kk * 32);
        }

        float mrow[2] = {-1e30f, -1e30f};
        float lrow[2] = {0.0f, 0.0f};
        float o[16][4];
#pragma unroll
        for (int g = 0; g < 16; g++)
#pragma unroll
            for (int r = 0; r < 4; r++) o[g][r] = 0.0f;

#pragma unroll 1
        for (int t = 0; t < ntiles; t++) {
            const int bufi = t & 1;
            if (t + 1 < ntiles) { CP_ASYNC_WAIT(1); } else { CP_ASYNC_WAIT(0); }
            __syncthreads();
            const uint32_t sK  = sSt + bufi * ATT_STAGE;
            const uint32_t sKl = sK + KTILE;
            const uint32_t sV  = sK + 2 * KTILE;

            float s[8][4];
#pragma unroll
            for (int nt = 0; nt < 8; nt++)
#pragma unroll
                for (int r = 0; r < 4; r++) s[nt][r] = 0.0f;

#pragma unroll
            for (int kk = 0; kk < 8; kk++) {
                uint32_t bh[4][4], bl[4][4];
#pragma unroll
                for (int g = 0; g < 4; g++) {
                    ldsm_x4(bh[g], sK  + g * (16 * KROWB) + lrowk + kk * 32);
                    ldsm_x4(bl[g], sKl + g * (16 * KROWB) + lrowk + kk * 32);
                }
#pragma unroll
                for (int g = 0; g < 4; g++) {
                    mma_bf16(s[2 * g],     qh[kk], bh[g][0], bh[g][2]);
                    mma_bf16(s[2 * g + 1], qh[kk], bh[g][1], bh[g][3]);
                }
#pragma unroll
                for (int g = 0; g < 4; g++) {
                    mma_bf16(s[2 * g],     qh[kk], bl[g][0], bl[g][2]);
                    mma_bf16(s[2 * g + 1], qh[kk], bl[g][1], bl[g][3]);
                }
#pragma unroll
                for (int g = 0; g < 4; g++) {
                    mma_bf16(s[2 * g],     ql[kk], bh[g][0], bh[g][2]);
                    mma_bf16(s[2 * g + 1], ql[kk], bh[g][1], bh[g][3]);
                }
            }

#pragma unroll
            for (int i = 0; i < 2; i++) {
                float mx = mrow[i];
#pragma unroll
                for (int nt = 0; nt < 8; nt++)
                    mx = fmaxf(mx, fmaxf(s[nt][2 * i], s[nt][2 * i + 1]));
                mx = fmaxf(mx, __shfl_xor_sync(0xffffffffu, mx, 1));
                mx = fmaxf(mx, __shfl_xor_sync(0xffffffffu, mx, 2));
                const float alpha = __expf(mrow[i] - mx);
                mrow[i] = mx;
                float rs = 0.0f;
#pragma unroll
                for (int nt = 0; nt < 8; nt++) {
                    float p0 = __expf(s[nt][2 * i] - mx);
                    float p1 = __expf(s[nt][2 * i + 1] - mx);
                    s[nt][2 * i] = p0; s[nt][2 * i + 1] = p1;
                    rs += p0 + p1;
                }
                rs += __shfl_xor_sync(0xffffffffu, rs, 1);
                rs += __shfl_xor_sync(0xffffffffu, rs, 2);
                lrow[i] = lrow[i] * alpha + rs;
#pragma unroll
                for (int nt = 0; nt < 16; nt++) {
                    o[nt][2 * i] *= alpha; o[nt][2 * i + 1] *= alpha;
                }
            }

            uint32_t pa[4][4];
#pragma unroll
            for (int j = 0; j < 4; j++) {
                pa[j][0] = packf16(s[2 * j][0],     s[2 * j][1]);
                pa[j][1] = packf16(s[2 * j][2],     s[2 * j][3]);
                pa[j][2] = packf16(s[2 * j + 1][0], s[2 * j + 1][1]);
                pa[j][3] = packf16(s[2 * j + 1][2], s[2 * j + 1][3]);
            }

#pragma unroll
            for (int j = 0; j < 4; j++) {
#pragma unroll
                for (int g = 0; g < 8; g++) {
                    uint32_t vb[4];
                    ldsm_x4(vb, sV + g * (16 * VROWB) + lrowv + j * 32);
                    mma_f16(o[2 * g],     pa[j], vb[0], vb[2]);
                    mma_f16(o[2 * g + 1], pa[j], vb[1], vb[3]);
                }
            }
            __syncthreads();
            if (t + 2 < ntiles) load_kv(bufi, t + 2);
        }

        const float inv0 = 1.0f / lrow[0];
        const float inv1 = 1.0f / lrow[1];

        if (pass == 0) {
            // hold pass-0 output in registers (packed fp16x2)
#pragma unroll
            for (int g = 0; g < 16; g++) {
                acc16[g][0] = packf16(o[g][0] * inv0, o[g][1] * inv0);
                acc16[g][1] = packf16(o[g][2] * inv1, o[g][3] * inv1);
            }
        } else {
            const int r0 = q0 + w * 16 + (lane >> 2);
            const int cb = hofs + (lane & 3) * 2;
#pragma unroll
            for (int g = 0; g < 16; g++) {
                const size_t i0 = (size_t)r0 * HIDN + cb + g * 8;
                const size_t i1 = (size_t)(r0 + 8) * HIDN + cb + g * 8;
                float a00, a01, a10, a11;
                unpackf16(acc16[g][0], a00, a01);
                unpackf16(acc16[g][1], a10, a11);
                const float v00 = a00 + o[g][0] * inv0;
                const float v01 = a01 + o[g][1] * inv0;
                const float v10 = a10 + o[g][2] * inv1;
                const float v11 = a11 + o[g][3] * inv1;
                const __half h00 = __float2half(v00), h01 = __float2half(v01);
                const __half h10 = __float2half(v10), h11 = __float2half(v11);
                __half2 hh0; hh0.x = h00; hh0.y = h01;
                __half2 hh1; hh1.x = h10; hh1.y = h11;
                __half2 hl0; hl0.x = __float2half(v00 - __half2float(h00));
                hl0.y = __float2half(v01 - __half2float(h01));
                __half2 hl1; hl1.x = __float2half(v10 - __half2float(h10));
                hl1.y = __float2half(v11 - __half2float(h11));
                *(__half2*)(out16_hi + i0) = hh0;
                *(__half2*)(out16_hi + i1) = hh1;
                *(__half2*)(out16_lo + i0) = hl0;
                *(__half2*)(out16_lo + i1) = hl1;
            }
        }
    }
}

// ---------------------------------------------------------------------------
// Launch: two-stream fork/join (R12 structure)
// ---------------------------------------------------------------------------
extern "C" void kernel_launch(void* const* d_in, const int* in_sizes, int n_in,
                              void* d_out, int out_size)
{
    const float* hidden = (const float*)d_in[0];
    const float* iph    = (const float*)d_in[1];
    const float* sinp   = (const float*)d_in[2];
    const float* cosp   = (const float*)d_in[3];
    const float* Wq     = (const float*)d_in[4];
    const float* bq     = (const float*)d_in[5];
    const float* Wk     = (const float*)d_in[6];
    const float* bk     = (const float*)d_in[7];
    const float* Wv     = (const float*)d_in[8];
    const float* bv     = (const float*)d_in[9];
    const float* Wo     = (const float*)d_in[10];
    const float* bo     = (const float*)d_in[11];
    const float* Wk_ip  = (const float*)d_in[12];
    const float* bk_ip  = (const float*)d_in[13];
    const float* Wv_ip  = (const float*)d_in[14];
    const float* bv_ip  = (const float*)d_in[15];
    const float* qscale = (const float*)d_in[16];
    const float* kscale = (const float*)d_in[17];

    float *q, *k, *kip;
    cudaGetSymbolAddress((void**)&q,    g_q);
    cudaGetSymbolAddress((void**)&k,    g_k);
    cudaGetSymbolAddress((void**)&kip,  g_kip);

    __nv_bfloat16 *hb_hi, *hb_lo, *wq_hi, *wq_lo, *wk_hi, *wk_lo,
                  *wkip_hi, *wkip_lo, *ip_hi, *ip_lo;
    __nv_bfloat16 *qr_hi, *qr_lo, *qn_hi, *qn_lo, *kr_hi, *kr_lo, *kipn_hi, *kipn_lo;
    __half *hb16_hi, *hb16_lo, *ip16_hi, *ip16_lo, *wv16, *wvip16, *wo16,
           *ao16_hi, *ao16_lo, *vt, *vipt;
    cudaGetSymbolAddress((void**)&hb_hi,   g_hb_hi);
    cudaGetSymbolAddress((void**)&hb_lo,   g_hb_lo);
    cudaGetSymbolAddress((void**)&wq_hi,   g_wq_hi);
    cudaGetSymbolAddress((void**)&wq_lo,   g_wq_lo);
    cudaGetSymbolAddress((void**)&wk_hi,   g_wk_hi);
    cudaGetSymbolAddress((void**)&wk_lo,   g_wk_lo);
    cudaGetSymbolAddress((void**)&wkip_hi, g_wkip_hi);
    cudaGetSymbolAddress((void**)&wkip_lo, g_wkip_lo);
    cudaGetSymbolAddress((void**)&ip_hi,   g_ip_hi);
    cudaGetSymbolAddress((void**)&ip_lo,   g_ip_lo);
    cudaGetSymbolAddress((void**)&qr_hi,   g_qr_hi);
    cudaGetSymbolAddress((void**)&qr_lo,   g_qr_lo);
    cudaGetSymbolAddress((void**)&qn_hi,   g_qn_hi);
    cudaGetSymbolAddress((void**)&qn_lo,   g_qn_lo);
    cudaGetSymbolAddress((void**)&kr_hi,   g_kr_hi);
    cudaGetSymbolAddress((void**)&kr_lo,   g_kr_lo);
    cudaGetSymbolAddress((void**)&kipn_hi, g_kipn_hi);
    cudaGetSymbolAddress((void**)&kipn_lo, g_kipn_lo);
    cudaGetSymbolAddress((void**)&hb16_hi, g_hb16_hi);
    cudaGetSymbolAddress((void**)&hb16_lo, g_hb16_lo);
    cudaGetSymbolAddress((void**)&ip16_hi, g_ip16_hi);
    cudaGetSymbolAddress((void**)&ip16_lo, g_ip16_lo);
    cudaGetSymbolAddress((void**)&wv16,    g_wv16);
    cudaGetSymbolAddress((void**)&wvip16,  g_wvip16);
    cudaGetSymbolAddress((void**)&wo16,    g_wo16);
    cudaGetSymbolAddress((void**)&ao16_hi, g_ao16_hi);
    cudaGetSymbolAddress((void**)&ao16_lo, g_ao16_lo);
    cudaGetSymbolAddress((void**)&vt,      g_vt);
    cudaGetSymbolAddress((void**)&vipt,    g_vipt);

    static cudaStream_t sB = nullptr;
    static cudaEvent_t evFork = nullptr, evJoin = nullptr;
    if (!sB) {
        cudaStreamCreateWithFlags(&sB, cudaStreamNonBlocking);
        cudaEventCreateWithFlags(&evFork, cudaEventDisableTiming);
        cudaEventCreateWithFlags(&evJoin, cudaEventDisableTiming);
    }

    const int n4w   = HIDN * HIDN / 4;
    const int n4ipw = HIDN * IPDIM / 4;
    const int n4h   = S_LEN * HIDN / 4;
    const int n4ip  = IPSEQ * IPDIM / 4;

    cudaFuncSetAttribute(gemm_mma_f, cudaFuncAttributeMaxDynamicSharedMemorySize, GEMM_DSMEM);
    cudaFuncSetAttribute(attn_mma, cudaFuncAttributeMaxDynamicSharedMemorySize, ATT_SMEM);

    cudaEventRecord(evFork, 0);
    cudaStreamWaitEvent(sB, evFork, 0);

    // ---- stream A: conversions for QKV path ----
    {
        MSet a = { Wq, wq_hi, wq_lo, nullptr, nullptr, n4w, 0 };
        MSet b = { Wk, wk_hi, wk_lo, nullptr, nullptr, n4w, 0 };
        MSet c = { hidden, hb_hi, hb_lo, hb16_hi, hb16_lo, n4h, 3 };
        MSet d = { Wv, wv16, nullptr, nullptr, nullptr, n4w, 2 };
        cvt_mixed<<<dim3((n4w + 255) / 256, 4), 256>>>(a, b, c, d);
    }
    // ---- stream B: conversions for IP + Wo paths ----
    {
        MSet a = { Wk_ip, wkip_hi, wkip_lo, nullptr, nullptr, n4ipw, 0 };
        MSet b = { iph, ip_hi, ip_lo, ip16_hi, ip16_lo, n4ip, 3 };
        MSet c = { Wv_ip, wvip16, nullptr, nullptr, nullptr, n4ipw, 2 };
        MSet d = { Wo, wo16, nullptr, nullptr, nullptr, n4w, 2 };
        cvt_mixed<<<dim3((n4w + 255) / 256, 4), 256, 0, sB>>>(a, b, c, d);
    }

    // ---- stream A: fused QKV projection (V writes fp16 transposed vt) ----
    {
        GSet sq = { (const uint16_t*)hb_hi,   (const uint16_t*)hb_lo,
                    (const uint16_t*)wq_hi,   (const uint16_t*)wq_lo,   bq, q,
                    nullptr, 0, 0 };
        GSet sk = { (const uint16_t*)hb_hi,   (const uint16_t*)hb_lo,
                    (const uint16_t*)wk_hi,   (const uint16_t*)wk_lo,   bk, k,
                    nullptr, 0, 0 };
        GSet sv = { (const uint16_t*)hb16_hi, (const uint16_t*)hb16_lo,
                    (const uint16_t*)wv16,    nullptr,                  bv, nullptr,
                    vt, S_LEN, 1 };
        gemm_mma_f<<<dim3(3 * (HIDN / 128), S_LEN / 128), 256, GEMM_DSMEM>>>(
            sq, sk, sv, HIDN / 128, HIDN, HIDN);
    }
    // ---- stream B: fused IP projection (Vip writes fp16 transposed vipt) ----
    {
        GSet sk = { (const uint16_t*)ip_hi,   (const uint16_t*)ip_lo,
                    (const uint16_t*)wkip_hi, (const uint16_t*)wkip_lo, bk_ip, kip,
                    nullptr, 0, 0 };
        GSet sv = { (const uint16_t*)ip16_hi, (const uint16_t*)ip16_lo,
                    (const uint16_t*)wvip16,  nullptr,                  bv_ip, nullptr,
                    vipt, IPSEQ, 1 };
        gemm_mma_f<<<dim3(2 * (HIDN / 128), IPSEQ / 128), 256, GEMM_DSMEM, sB>>>(
            sk, sv, sv, HIDN / 128, HIDN, IPDIM);
    }

    // ---- stream A: Q/K prep ----
    prep_qk_kernel<<<dim3(S_LEN, NH), 128>>>(q, k, sinp, cosp, qscale,
                                             qr_hi, qr_lo, qn_hi, qn_lo, kr_hi, kr_lo);

    // ---- stream B: Kip prep ----
    prep_kip_kernel<<<dim3(IPSEQ, NH), 128, 0, sB>>>(kip, kscale, kipn_hi, kipn_lo);

    // ---- join ----
    cudaEventRecord(evJoin, sB);
    cudaStreamWaitEvent(0, evJoin, 0);

    // ---- attention (register-resident cross-pass acc; writes ao16 only) ----
    attn_mma<<<dim3(S_LEN / 128, NH), 256, ATT_SMEM>>>(
        qr_hi, qr_lo, qn_hi, qn_lo, kr_hi, kr_lo, kipn_hi, kipn_lo, vt, vipt,
        ao16_hi, ao16_lo);

    // ---- output projection (fp16 2-term) ----
    {
        GSet so = { (const uint16_t*)ao16_hi, (const uint16_t*)ao16_lo,
                    (const uint16_t*)wo16,    nullptr, bo, (float*)d_out,
                    nullptr, 0, 1 };
        gemm_mma_f<<<dim3(HIDN / 128, S_LEN / 128), 256, GEMM_DSMEM>>>(
            so, so, so, HIDN / 128, HIDN, HIDN);
    }
}